// round 6
// baseline (speedup 1.0000x reference)
#include <cuda_runtime.h>
#include <cuda_fp16.h>
#include <cstdint>

#define B_   4
#define N_   2048
#define E_   1024
#define H_   16
#define D_   64
#define HID_ 4096
#define M_   (B_*N_)   // 8192 rows

// ---------------- device scratch (static globals: allocation-free) ----------
__device__ __half g_h   [M_*E_];                 // LN1 out (fp16)
__device__ __half g_qkv [(size_t)M_*3*E_];       // QKV (fp16)
__device__ __half g_attn[M_*E_];                 // attention context (fp16)
__device__ float  g_res1[M_*E_];                 // attn proj + x (fp32)
__device__ __half g_h2  [M_*E_];                 // LN2 out (fp16)
__device__ __half g_z   [(size_t)M_*HID_];       // gelu(h2@w0) (fp16)
__device__ __half g_wqkv[E_*3*E_];               // transposed [3E][E] K-major
__device__ __half g_wproj[E_*E_];                // transposed [E][E]
__device__ __half g_w0  [E_*HID_];               // transposed [HID][E]
__device__ __half g_w1  [HID_*E_];               // transposed [E][HID]
__device__ __half g_bqkv[3*E_];
__device__ __half g_bproj[E_];
__device__ __half g_b0  [HID_];
__device__ __half g_b1  [E_];

// ---------------- helpers ---------------------------------------------------
__device__ __forceinline__ void cp16s(unsigned smem_dst, const void* gsrc) {
    asm volatile("cp.async.cg.shared.global [%0], [%1], 16;\n" :: "r"(smem_dst), "l"(gsrc));
}
__device__ __forceinline__ void cp_commit() { asm volatile("cp.async.commit_group;\n"); }

__device__ __forceinline__ void ldmx4(uint32_t addr, uint32_t& r0, uint32_t& r1, uint32_t& r2, uint32_t& r3) {
    asm volatile("ldmatrix.sync.aligned.m8n8.x4.shared.b16 {%0,%1,%2,%3}, [%4];\n"
                 : "=r"(r0), "=r"(r1), "=r"(r2), "=r"(r3) : "r"(addr));
}
__device__ __forceinline__ void ldmx4t(uint32_t addr, uint32_t& r0, uint32_t& r1, uint32_t& r2, uint32_t& r3) {
    asm volatile("ldmatrix.sync.aligned.m8n8.x4.trans.shared.b16 {%0,%1,%2,%3}, [%4];\n"
                 : "=r"(r0), "=r"(r1), "=r"(r2), "=r"(r3) : "r"(addr));
}
__device__ __forceinline__ void mma16816(float* c, const uint32_t* a, uint32_t b0, uint32_t b1) {
    asm volatile("mma.sync.aligned.m16n8k16.row.col.f32.f16.f16.f32 "
                 "{%0,%1,%2,%3},{%4,%5,%6,%7},{%8,%9},{%0,%1,%2,%3};\n"
                 : "+f"(c[0]), "+f"(c[1]), "+f"(c[2]), "+f"(c[3])
                 : "r"(a[0]), "r"(a[1]), "r"(a[2]), "r"(a[3]), "r"(b0), "r"(b1));
}
__device__ __forceinline__ uint32_t swz(int row, int col) {
    return (uint32_t)(row * 128 + ((((col >> 3) ^ (row & 7)) << 4) | ((col & 7) * 2)));
}

// ---------------- elementwise cast fp32 -> fp16 ------------------------------
__global__ void cast_f2h(const float* __restrict__ in, __half* __restrict__ out, int n) {
    int stride = gridDim.x * blockDim.x;
    for (int i = blockIdx.x * blockDim.x + threadIdx.x; i < n; i += stride)
        out[i] = __float2half(in[i]);
}

// ---------------- cast + transpose: [K][N] fp32 -> [N][K] fp16 ---------------
__global__ __launch_bounds__(256) void cast_transpose(const float* __restrict__ in,
                                                      __half* __restrict__ out,
                                                      int K, int N) {
    __shared__ float t[32][33];
    int n0 = blockIdx.x * 32, k0 = blockIdx.y * 32;
    int tx = threadIdx.x & 31, ty = threadIdx.x >> 5;   // 32 x 8
    #pragma unroll
    for (int i = 0; i < 4; i++)
        t[ty + i * 8][tx] = in[(size_t)(k0 + ty + i * 8) * N + n0 + tx];
    __syncthreads();
    #pragma unroll
    for (int i = 0; i < 4; i++)
        out[(size_t)(n0 + ty + i * 8) * K + k0 + tx] = __float2half(t[tx][ty + i * 8]);
}

// ---------------- LayerNorm (fp32 in, fp16 out), one block per row -----------
__global__ __launch_bounds__(256) void ln_kernel(const float* __restrict__ x,
                                                 const float* __restrict__ gam,
                                                 const float* __restrict__ bet,
                                                 __half* __restrict__ out) {
    int row = blockIdx.x;
    int t = threadIdx.x;
    const float4 v  = ((const float4*)(x + (size_t)row * E_))[t];
    float s  = v.x + v.y + v.z + v.w;
    float ss = v.x*v.x + v.y*v.y + v.z*v.z + v.w*v.w;

    __shared__ float r0[8], r1[8];
    int w = t >> 5, l = t & 31;
    #pragma unroll
    for (int o = 16; o; o >>= 1) {
        s  += __shfl_xor_sync(0xffffffffu, s,  o);
        ss += __shfl_xor_sync(0xffffffffu, ss, o);
    }
    if (l == 0) { r0[w] = s; r1[w] = ss; }
    __syncthreads();
    if (t < 32) {
        float a = (l < 8) ? r0[l] : 0.f;
        float b = (l < 8) ? r1[l] : 0.f;
        #pragma unroll
        for (int o = 4; o; o >>= 1) {
            a += __shfl_xor_sync(0xffffffffu, a, o);
            b += __shfl_xor_sync(0xffffffffu, b, o);
        }
        if (l == 0) { r0[0] = a; r1[0] = b; }
    }
    __syncthreads();
    float mu  = r0[0] * (1.0f / E_);
    float var = r1[0] * (1.0f / E_) - mu * mu;
    float rs  = rsqrtf(var + 1e-5f);

    const float4 gv = ((const float4*)gam)[t];
    const float4 bv = ((const float4*)bet)[t];
    __half* op = out + (size_t)row * E_ + t * 4;
    op[0] = __float2half((v.x - mu) * rs * gv.x + bv.x);
    op[1] = __float2half((v.y - mu) * rs * gv.y + bv.y);
    op[2] = __float2half((v.z - mu) * rs * gv.z + bv.z);
    op[3] = __float2half((v.w - mu) * rs * gv.w + bv.w);
}

// ---------------- fused flash attention (validated round 3) ------------------
__global__ __launch_bounds__(256) void flash_attn_kernel(
    const __half* __restrict__ qkv, __half* __restrict__ outp)
{
    __shared__ __align__(128) __half Qs[128 * 64];
    __shared__ __align__(128) __half Ks[2][64 * 64];
    __shared__ __align__(128) __half Vs[2][64 * 64];

    const int z = blockIdx.y;
    const int b = z >> 4, h = z & 15;
    const __half* qb = qkv + (size_t)b * N_ * 3 * E_ + h * D_;
    const __half* kb = qb + E_;
    const __half* vb = qb + 2 * E_;
    const int q0 = blockIdx.x * 128;

    const int tid = threadIdx.x;
    const int warp = tid >> 5, lane = tid & 31;

    const uint32_t sQ = (uint32_t)__cvta_generic_to_shared(Qs);
    const uint32_t sK[2] = { (uint32_t)__cvta_generic_to_shared(Ks[0]),
                             (uint32_t)__cvta_generic_to_shared(Ks[1]) };
    const uint32_t sV[2] = { (uint32_t)__cvta_generic_to_shared(Vs[0]),
                             (uint32_t)__cvta_generic_to_shared(Vs[1]) };

    #pragma unroll
    for (int i = 0; i < 4; i++) {
        int ch = tid + i * 256;
        int r = ch >> 3, c = ch & 7;
        cp16s(sQ + r * 128 + ((c ^ (r & 7)) << 4),
              qb + (size_t)(q0 + r) * (3 * E_) + c * 8);
    }
    auto loadKV = [&](int buf, int kv0) {
        #pragma unroll
        for (int i = 0; i < 2; i++) {
            int ch = tid + i * 256;
            int r = ch >> 3, c = ch & 7;
            uint32_t off = r * 128 + ((c ^ (r & 7)) << 4);
            cp16s(sK[buf] + off, kb + (size_t)(kv0 + r) * (3 * E_) + c * 8);
            cp16s(sV[buf] + off, vb + (size_t)(kv0 + r) * (3 * E_) + c * 8);
        }
    };
    loadKV(0, 0);
    cp_commit();
    asm volatile("cp.async.wait_group 0;\n");
    __syncthreads();

    uint32_t qf[4][4];
    {
        int r = warp * 16 + (lane & 7) + ((lane & 8) ? 8 : 0);
        int kc = ((lane & 16) ? 8 : 0);
        #pragma unroll
        for (int ks = 0; ks < 4; ks++)
            ldmx4(sQ + swz(r, ks * 16 + kc), qf[ks][0], qf[ks][1], qf[ks][2], qf[ks][3]);
    }

    float m0 = -1e30f, m1 = -1e30f;
    float l0 = 0.f, l1 = 0.f;
    float oacc[8][4];
    #pragma unroll
    for (int j = 0; j < 8; j++)
        #pragma unroll
        for (int c = 0; c < 4; c++) oacc[j][c] = 0.f;

    const int ITERS = N_ / 64;
    for (int it = 0; it < ITERS; ++it) {
        int cur = it & 1;
        if (it + 1 < ITERS) {
            loadKV(cur ^ 1, (it + 1) * 64);
            cp_commit();
            asm volatile("cp.async.wait_group 1;\n");
        } else {
            asm volatile("cp.async.wait_group 0;\n");
        }
        __syncthreads();

        float sacc[8][4];
        #pragma unroll
        for (int j = 0; j < 8; j++)
            #pragma unroll
            for (int c = 0; c < 4; c++) sacc[j][c] = 0.f;

        const int g = lane >> 3;
        #pragma unroll
        for (int j2 = 0; j2 < 4; j2++) {
            int nr = j2 * 16 + ((g >> 1) << 3) + (lane & 7);
            #pragma unroll
            for (int ks = 0; ks < 4; ks++) {
                uint32_t b0, b1, b2, b3;
                ldmx4(sK[cur] + swz(nr, ks * 16 + ((g & 1) << 3)), b0, b1, b2, b3);
                mma16816(sacc[2 * j2],     qf[ks], b0, b1);
                mma16816(sacc[2 * j2 + 1], qf[ks], b2, b3);
            }
        }

        float f0x[8], f0y[8], f1x[8], f1y[8];
        float mx0 = -1e30f, mx1 = -1e30f;
        #pragma unroll
        for (int j = 0; j < 8; j++) {
            __half2 h0 = __floats2half2_rn(sacc[j][0], sacc[j][1]);
            __half2 h1 = __floats2half2_rn(sacc[j][2], sacc[j][3]);
            float2 g0 = __half22float2(h0);
            float2 g1 = __half22float2(h1);
            f0x[j] = g0.x; f0y[j] = g0.y; f1x[j] = g1.x; f1y[j] = g1.y;
            mx0 = fmaxf(mx0, fmaxf(g0.x, g0.y));
            mx1 = fmaxf(mx1, fmaxf(g1.x, g1.y));
        }
        mx0 = fmaxf(mx0, __shfl_xor_sync(0xffffffffu, mx0, 1));
        mx0 = fmaxf(mx0, __shfl_xor_sync(0xffffffffu, mx0, 2));
        mx1 = fmaxf(mx1, __shfl_xor_sync(0xffffffffu, mx1, 1));
        mx1 = fmaxf(mx1, __shfl_xor_sync(0xffffffffu, mx1, 2));

        float m0n = fmaxf(m0, mx0), m1n = fmaxf(m1, mx1);
        float sc0 = __expf(m0 - m0n), sc1 = __expf(m1 - m1n);

        uint32_t pu0[8], pu1[8];
        float sum0 = 0.f, sum1 = 0.f;
        #pragma unroll
        for (int j = 0; j < 8; j++) {
            float p00 = __expf(f0x[j] - m0n), p01 = __expf(f0y[j] - m0n);
            float p10 = __expf(f1x[j] - m1n), p11 = __expf(f1y[j] - m1n);
            sum0 += p00 + p01;
            sum1 += p10 + p11;
            __half2 hp0 = __floats2half2_rn(p00, p01);
            __half2 hp1 = __floats2half2_rn(p10, p11);
            pu0[j] = *reinterpret_cast<uint32_t*>(&hp0);
            pu1[j] = *reinterpret_cast<uint32_t*>(&hp1);
        }
        sum0 += __shfl_xor_sync(0xffffffffu, sum0, 1);
        sum0 += __shfl_xor_sync(0xffffffffu, sum0, 2);
        sum1 += __shfl_xor_sync(0xffffffffu, sum1, 1);
        sum1 += __shfl_xor_sync(0xffffffffu, sum1, 2);

        l0 = l0 * sc0 + sum0;
        l1 = l1 * sc1 + sum1;
        m0 = m0n; m1 = m1n;

        #pragma unroll
        for (int j = 0; j < 8; j++) {
            oacc[j][0] *= sc0; oacc[j][1] *= sc0;
            oacc[j][2] *= sc1; oacc[j][3] *= sc1;
        }

        #pragma unroll
        for (int j2 = 0; j2 < 4; j2++) {
            int dc = j2 * 16 + ((g >> 1) << 3);
            #pragma unroll
            for (int kk = 0; kk < 4; kk++) {
                uint32_t b0, b1, b2, b3;
                ldmx4t(sV[cur] + swz(kk * 16 + ((g & 1) << 3) + (lane & 7), dc), b0, b1, b2, b3);
                uint32_t a[4] = { pu0[2 * kk], pu1[2 * kk], pu0[2 * kk + 1], pu1[2 * kk + 1] };
                mma16816(oacc[2 * j2],     a, b0, b1);
                mma16816(oacc[2 * j2 + 1], a, b2, b3);
            }
        }
        __syncthreads();
    }

    float inv0 = 1.0f / l0, inv1 = 1.0f / l1;
    int r0g = q0 + warp * 16 + (lane >> 2);
    int r1g = r0g + 8;
    __half* ob = outp + (size_t)b * N_ * E_ + h * 64 + (lane & 3) * 2;
    #pragma unroll
    for (int j = 0; j < 8; j++) {
        __half2 v0 = __floats2half2_rn(oacc[j][0] * inv0, oacc[j][1] * inv0);
        __half2 v1 = __floats2half2_rn(oacc[j][2] * inv1, oacc[j][3] * inv1);
        *reinterpret_cast<__half2*>(ob + (size_t)r0g * E_ + j * 8) = v0;
        *reinterpret_cast<__half2*>(ob + (size_t)r1g * E_ + j * 8) = v1;
    }
}

// ---------------- gemm3: BM=128, BN=256, BK=64, warp tile 64x64, 3 stages ----
// A: [M][K] fp16 K-major. Bt: [N][K] fp16 K-major (pre-transposed weights).
enum { EPI_F16 = 0, EPI_GELU = 1, EPI_RES = 2 };

#define G3_STAGE 49152                 // A 16KB + B 32KB
#define G3_SMEM  (3 * G3_STAGE)

template<int EPI>
__global__ __launch_bounds__(256) void gemm3(
    const __half* __restrict__ A, int lda,
    const __half* __restrict__ Bt,
    const __half* __restrict__ bias,
    void* __restrict__ Cout, int ldc,
    const float* __restrict__ res, int K)
{
    extern __shared__ __align__(128) char dsm[];

    const int tid = threadIdx.x;
    const int warp = tid >> 5, lane = tid & 31;
    const int wm = warp & 1, wn = warp >> 1;          // 2 x 4 warp grid
    const int rowBase = blockIdx.y * 128;
    const int colBase = blockIdx.x * 256;

    const uint32_t sbase = (uint32_t)__cvta_generic_to_shared(dsm);

    auto loadA = [&](int s, int k0) {
        uint32_t bptr = sbase + s * G3_STAGE;
        #pragma unroll
        for (int i = 0; i < 4; i++) {
            int ch = tid + i * 256;                    // 128 rows x 8 chunks
            int r = ch >> 3, c = ch & 7;
            cp16s(bptr + r * 128 + ((c ^ (r & 7)) << 4),
                  A + (size_t)(rowBase + r) * lda + k0 + c * 8);
        }
    };
    auto loadB = [&](int s, int k0) {
        uint32_t bptr = sbase + s * G3_STAGE + 16384;
        #pragma unroll
        for (int i = 0; i < 8; i++) {
            int ch = tid + i * 256;                    // 256 rows x 8 chunks
            int r = ch >> 3, c = ch & 7;
            cp16s(bptr + r * 128 + ((c ^ (r & 7)) << 4),
                  Bt + (size_t)(colBase + r) * K + k0 + c * 8);
        }
    };

    float acc[4][8][4];
    #pragma unroll
    for (int mi = 0; mi < 4; mi++)
        #pragma unroll
        for (int j = 0; j < 8; j++)
            #pragma unroll
            for (int c = 0; c < 4; c++) acc[mi][j][c] = 0.f;

    const int KT = K / 64;
    loadA(0, 0);   loadB(0, 0);   cp_commit();
    loadA(1, 64);  loadB(1, 64);  cp_commit();

    const int g = lane >> 3;
    for (int it = 0; it < KT; ++it) {
        asm volatile("cp.async.wait_group 1;\n");
        __syncthreads();
        if (it + 2 < KT) { loadA((it + 2) % 3, (it + 2) * 64); loadB((it + 2) % 3, (it + 2) * 64); cp_commit(); }

        const uint32_t aoff = sbase + (it % 3) * G3_STAGE;
        const uint32_t boff = aoff + 16384;
        #pragma unroll
        for (int ks = 0; ks < 4; ks++) {
            // B frags: warp covers cols wn*64 .. wn*64+63 -> 4 n16 groups
            uint32_t bf[4][4];
            #pragma unroll
            for (int j2 = 0; j2 < 4; j2++) {
                int nr = wn * 64 + j2 * 16 + ((g >> 1) << 3) + (lane & 7);
                ldmx4(boff + swz(nr, ks * 16 + ((g & 1) << 3)),
                      bf[j2][0], bf[j2][1], bf[j2][2], bf[j2][3]);
            }
            // A frags + mma
            #pragma unroll
            for (int mi = 0; mi < 4; mi++) {
                uint32_t af[4];
                int r = wm * 64 + mi * 16 + (lane & 15);
                ldmx4(aoff + swz(r, ks * 16 + ((lane >> 4) << 3)), af[0], af[1], af[2], af[3]);
                #pragma unroll
                for (int j2 = 0; j2 < 4; j2++) {
                    mma16816(acc[mi][2 * j2],     af, bf[j2][0], bf[j2][1]);
                    mma16816(acc[mi][2 * j2 + 1], af, bf[j2][2], bf[j2][3]);
                }
            }
        }
    }

    // ---- direct register epilogue ----
    #pragma unroll
    for (int mi = 0; mi < 4; mi++) {
        int gr0 = rowBase + wm * 64 + mi * 16 + (lane >> 2);
        int gr1 = gr0 + 8;
        #pragma unroll
        for (int j = 0; j < 8; j++) {
            int gc = colBase + wn * 64 + j * 8 + (lane & 3) * 2;
            __half2 hb = *reinterpret_cast<const __half2*>(bias + gc);
            float2 fb = __half22float2(hb);
            float v0 = acc[mi][j][0] + fb.x, v1 = acc[mi][j][1] + fb.y;
            float v2 = acc[mi][j][2] + fb.x, v3 = acc[mi][j][3] + fb.y;
            size_t o0 = (size_t)gr0 * ldc + gc;
            size_t o1 = (size_t)gr1 * ldc + gc;
            if (EPI == EPI_F16) {
                *reinterpret_cast<__half2*>((__half*)Cout + o0) = __floats2half2_rn(v0, v1);
                *reinterpret_cast<__half2*>((__half*)Cout + o1) = __floats2half2_rn(v2, v3);
            } else if (EPI == EPI_GELU) {
                float f0 = __half2float(__float2half(v0));
                float f1 = __half2float(__float2half(v1));
                float f2 = __half2float(__float2half(v2));
                float f3 = __half2float(__float2half(v3));
                float g0 = 0.5f * f0 * (1.0f + erff(f0 * 0.70710678118654752f));
                float g1 = 0.5f * f1 * (1.0f + erff(f1 * 0.70710678118654752f));
                float g2 = 0.5f * f2 * (1.0f + erff(f2 * 0.70710678118654752f));
                float g3 = 0.5f * f3 * (1.0f + erff(f3 * 0.70710678118654752f));
                *reinterpret_cast<__half2*>((__half*)Cout + o0) = __floats2half2_rn(g0, g1);
                *reinterpret_cast<__half2*>((__half*)Cout + o1) = __floats2half2_rn(g2, g3);
            } else { // EPI_RES: fp32 out = fp16(acc+bias) + residual
                float2 r0v = *reinterpret_cast<const float2*>(res + o0);
                float2 r1v = *reinterpret_cast<const float2*>(res + o1);
                float2 w0v, w1v;
                w0v.x = __half2float(__float2half(v0)) + r0v.x;
                w0v.y = __half2float(__float2half(v1)) + r0v.y;
                w1v.x = __half2float(__float2half(v2)) + r1v.x;
                w1v.y = __half2float(__float2half(v3)) + r1v.y;
                *reinterpret_cast<float2*>((float*)Cout + o0) = w0v;
                *reinterpret_cast<float2*>((float*)Cout + o1) = w1v;
            }
        }
    }
}

// ---------------- launch ----------------------------------------------------
extern "C" void kernel_launch(void* const* d_in, const int* in_sizes, int n_in,
                              void* d_out, int out_size)
{
    const float* x      = (const float*)d_in[0];
    const float* ln1_g  = (const float*)d_in[1];
    const float* ln1_b  = (const float*)d_in[2];
    const float* wqkv   = (const float*)d_in[3];
    const float* bqkv   = (const float*)d_in[4];
    const float* wproj  = (const float*)d_in[5];
    const float* bproj  = (const float*)d_in[6];
    const float* ln2_g  = (const float*)d_in[7];
    const float* ln2_b  = (const float*)d_in[8];
    const float* w0     = (const float*)d_in[9];
    const float* b0     = (const float*)d_in[10];
    const float* w1     = (const float*)d_in[11];
    const float* b1     = (const float*)d_in[12];

    void *p_h, *p_qkv, *p_attn, *p_res1, *p_h2, *p_z;
    void *p_wqkv, *p_wproj, *p_w0, *p_w1, *p_bqkv, *p_bproj, *p_b0, *p_b1;
    cudaGetSymbolAddress(&p_h, g_h);
    cudaGetSymbolAddress(&p_qkv, g_qkv);
    cudaGetSymbolAddress(&p_attn, g_attn);
    cudaGetSymbolAddress(&p_res1, g_res1);
    cudaGetSymbolAddress(&p_h2, g_h2);
    cudaGetSymbolAddress(&p_z, g_z);
    cudaGetSymbolAddress(&p_wqkv, g_wqkv);
    cudaGetSymbolAddress(&p_wproj, g_wproj);
    cudaGetSymbolAddress(&p_w0, g_w0);
    cudaGetSymbolAddress(&p_w1, g_w1);
    cudaGetSymbolAddress(&p_bqkv, g_bqkv);
    cudaGetSymbolAddress(&p_bproj, g_bproj);
    cudaGetSymbolAddress(&p_b0, g_b0);
    cudaGetSymbolAddress(&p_b1, g_b1);

    static bool attr_done = false;
    if (!attr_done) {
        cudaFuncSetAttribute(gemm3<EPI_F16>,  cudaFuncAttributeMaxDynamicSharedMemorySize, G3_SMEM);
        cudaFuncSetAttribute(gemm3<EPI_GELU>, cudaFuncAttributeMaxDynamicSharedMemorySize, G3_SMEM);
        cudaFuncSetAttribute(gemm3<EPI_RES>,  cudaFuncAttributeMaxDynamicSharedMemorySize, G3_SMEM);
        attr_done = true;
    }

    // weight cast + transpose to [N][K] K-major
    cast_transpose<<<dim3(3 * E_ / 32, E_ / 32), 256>>>(wqkv,  (__half*)p_wqkv,  E_,   3 * E_);
    cast_transpose<<<dim3(E_ / 32,     E_ / 32), 256>>>(wproj, (__half*)p_wproj, E_,   E_);
    cast_transpose<<<dim3(HID_ / 32,   E_ / 32), 256>>>(w0,    (__half*)p_w0,    E_,   HID_);
    cast_transpose<<<dim3(E_ / 32,   HID_ / 32), 256>>>(w1,    (__half*)p_w1,    HID_, E_);
    cast_f2h<<<12, 256>>>(bqkv,  (__half*)p_bqkv,  3 * E_);
    cast_f2h<<<4,  256>>>(bproj, (__half*)p_bproj, E_);
    cast_f2h<<<16, 256>>>(b0,    (__half*)p_b0,    HID_);
    cast_f2h<<<4,  256>>>(b1,    (__half*)p_b1,    E_);

    // LN1
    ln_kernel<<<M_, 256>>>(x, ln1_g, ln1_b, (__half*)p_h);

    // QKV: [8192,1024] @ W^T -> [8192,3072]
    gemm3<EPI_F16><<<dim3(3 * E_ / 256, M_ / 128), 256, G3_SMEM>>>(
        (const __half*)p_h, E_, (const __half*)p_wqkv,
        (const __half*)p_bqkv, p_qkv, 3 * E_, nullptr, E_);

    // fused flash attention
    flash_attn_kernel<<<dim3(N_ / 128, B_ * H_), 256>>>(
        (const __half*)p_qkv, (__half*)p_attn);

    // proj + residual (fp32 out)
    gemm3<EPI_RES><<<dim3(E_ / 256, M_ / 128), 256, G3_SMEM>>>(
        (const __half*)p_attn, E_, (const __half*)p_wproj,
        (const __half*)p_bproj, p_res1, E_, x, E_);

    // LN2
    ln_kernel<<<M_, 256>>>((const float*)p_res1, ln2_g, ln2_b, (__half*)p_h2);

    // MLP up + gelu
    gemm3<EPI_GELU><<<dim3(HID_ / 256, M_ / 128), 256, G3_SMEM>>>(
        (const __half*)p_h2, E_, (const __half*)p_w0,
        (const __half*)p_b0, p_z, HID_, nullptr, E_);

    // MLP down + residual (fp32 out)
    gemm3<EPI_RES><<<dim3(E_ / 256, M_ / 128), 256, G3_SMEM>>>(
        (const __half*)p_z, HID_, (const __half*)p_w1,
        (const __half*)p_b1, d_out, E_, (const float*)p_res1, HID_);
}

// round 8
// speedup vs baseline: 1.0739x; 1.0739x over previous
#include <cuda_runtime.h>
#include <cuda_fp16.h>
#include <cstdint>

#define B_   4
#define N_   2048
#define E_   1024
#define H_   16
#define D_   64
#define HID_ 4096
#define M_   (B_*N_)   // 8192 rows

// ---------------- device scratch (static globals: allocation-free) ----------
__device__ __half g_h   [M_*E_];                 // LN1 out (fp16)
__device__ __half g_qkv [(size_t)M_*3*E_];       // QKV (fp16)
__device__ __half g_attn[M_*E_];                 // attention context (fp16)
__device__ float  g_res1[M_*E_];                 // attn proj + x (fp32)
__device__ __half g_h2  [M_*E_];                 // LN2 out (fp16)
__device__ __half g_z   [(size_t)M_*HID_];       // gelu(h2@w0) (fp16)
__device__ __half g_wqkv[E_*3*E_];
__device__ __half g_wproj[E_*E_];
__device__ __half g_w0  [E_*HID_];
__device__ __half g_w1  [HID_*E_];
__device__ __half g_bqkv[3*E_];
__device__ __half g_bproj[E_];
__device__ __half g_b0  [HID_];
__device__ __half g_b1  [E_];

// ---------------- helpers ---------------------------------------------------
__device__ __forceinline__ void cp16s(unsigned smem_dst, const void* gsrc) {
    asm volatile("cp.async.cg.shared.global [%0], [%1], 16;\n" :: "r"(smem_dst), "l"(gsrc));
}
__device__ __forceinline__ void cp16(void* smem_dst, const void* gsrc) {
    unsigned d = (unsigned)__cvta_generic_to_shared(smem_dst);
    asm volatile("cp.async.cg.shared.global [%0], [%1], 16;\n" :: "r"(d), "l"(gsrc));
}
__device__ __forceinline__ void cp_commit() { asm volatile("cp.async.commit_group;\n"); }

__device__ __forceinline__ void ldmx4(uint32_t addr, uint32_t& r0, uint32_t& r1, uint32_t& r2, uint32_t& r3) {
    asm volatile("ldmatrix.sync.aligned.m8n8.x4.shared.b16 {%0,%1,%2,%3}, [%4];\n"
                 : "=r"(r0), "=r"(r1), "=r"(r2), "=r"(r3) : "r"(addr));
}
__device__ __forceinline__ void ldmx4t(uint32_t addr, uint32_t& r0, uint32_t& r1, uint32_t& r2, uint32_t& r3) {
    asm volatile("ldmatrix.sync.aligned.m8n8.x4.trans.shared.b16 {%0,%1,%2,%3}, [%4];\n"
                 : "=r"(r0), "=r"(r1), "=r"(r2), "=r"(r3) : "r"(addr));
}
__device__ __forceinline__ void mma16816(float* c, const uint32_t* a, uint32_t b0, uint32_t b1) {
    asm volatile("mma.sync.aligned.m16n8k16.row.col.f32.f16.f16.f32 "
                 "{%0,%1,%2,%3},{%4,%5,%6,%7},{%8,%9},{%0,%1,%2,%3};\n"
                 : "+f"(c[0]), "+f"(c[1]), "+f"(c[2]), "+f"(c[3])
                 : "r"(a[0]), "r"(a[1]), "r"(a[2]), "r"(a[3]), "r"(b0), "r"(b1));
}
__device__ __forceinline__ uint32_t swz(int row, int col) {
    return (uint32_t)(row * 128 + ((((col >> 3) ^ (row & 7)) << 4) | ((col & 7) * 2)));
}

// ---------------- elementwise cast fp32 -> fp16 ------------------------------
__global__ void cast_f2h(const float* __restrict__ in, __half* __restrict__ out, int n) {
    int stride = gridDim.x * blockDim.x;
    for (int i = blockIdx.x * blockDim.x + threadIdx.x; i < n; i += stride)
        out[i] = __float2half(in[i]);
}

// ---------------- LayerNorm (fp32 in, fp16 out), one block per row -----------
__global__ __launch_bounds__(256) void ln_kernel(const float* __restrict__ x,
                                                 const float* __restrict__ gam,
                                                 const float* __restrict__ bet,
                                                 __half* __restrict__ out) {
    int row = blockIdx.x;
    int t = threadIdx.x;
    const float4 v  = ((const float4*)(x + (size_t)row * E_))[t];
    float s  = v.x + v.y + v.z + v.w;
    float ss = v.x*v.x + v.y*v.y + v.z*v.z + v.w*v.w;

    __shared__ float r0[8], r1[8];
    int w = t >> 5, l = t & 31;
    #pragma unroll
    for (int o = 16; o; o >>= 1) {
        s  += __shfl_xor_sync(0xffffffffu, s,  o);
        ss += __shfl_xor_sync(0xffffffffu, ss, o);
    }
    if (l == 0) { r0[w] = s; r1[w] = ss; }
    __syncthreads();
    if (t < 32) {
        float a = (l < 8) ? r0[l] : 0.f;
        float b = (l < 8) ? r1[l] : 0.f;
        #pragma unroll
        for (int o = 4; o; o >>= 1) {
            a += __shfl_xor_sync(0xffffffffu, a, o);
            b += __shfl_xor_sync(0xffffffffu, b, o);
        }
        if (l == 0) { r0[0] = a; r1[0] = b; }
    }
    __syncthreads();
    float mu  = r0[0] * (1.0f / E_);
    float var = r1[0] * (1.0f / E_) - mu * mu;
    float rs  = rsqrtf(var + 1e-5f);

    const float4 gv = ((const float4*)gam)[t];
    const float4 bv = ((const float4*)bet)[t];
    __half* op = out + (size_t)row * E_ + t * 4;
    op[0] = __float2half((v.x - mu) * rs * gv.x + bv.x);
    op[1] = __float2half((v.y - mu) * rs * gv.y + bv.y);
    op[2] = __float2half((v.z - mu) * rs * gv.z + bv.z);
    op[3] = __float2half((v.w - mu) * rs * gv.w + bv.w);
}

// ---------------- fused flash attention (validated round 3) ------------------
__global__ __launch_bounds__(256) void flash_attn_kernel(
    const __half* __restrict__ qkv, __half* __restrict__ outp)
{
    __shared__ __align__(128) __half Qs[128 * 64];
    __shared__ __align__(128) __half Ks[2][64 * 64];
    __shared__ __align__(128) __half Vs[2][64 * 64];

    const int z = blockIdx.y;
    const int b = z >> 4, h = z & 15;
    const __half* qb = qkv + (size_t)b * N_ * 3 * E_ + h * D_;
    const __half* kb = qb + E_;
    const __half* vb = qb + 2 * E_;
    const int q0 = blockIdx.x * 128;

    const int tid = threadIdx.x;
    const int warp = tid >> 5, lane = tid & 31;

    const uint32_t sQ = (uint32_t)__cvta_generic_to_shared(Qs);
    const uint32_t sK[2] = { (uint32_t)__cvta_generic_to_shared(Ks[0]),
                             (uint32_t)__cvta_generic_to_shared(Ks[1]) };
    const uint32_t sV[2] = { (uint32_t)__cvta_generic_to_shared(Vs[0]),
                             (uint32_t)__cvta_generic_to_shared(Vs[1]) };

    #pragma unroll
    for (int i = 0; i < 4; i++) {
        int ch = tid + i * 256;
        int r = ch >> 3, c = ch & 7;
        cp16s(sQ + r * 128 + ((c ^ (r & 7)) << 4),
              qb + (size_t)(q0 + r) * (3 * E_) + c * 8);
    }
    auto loadKV = [&](int buf, int kv0) {
        #pragma unroll
        for (int i = 0; i < 2; i++) {
            int ch = tid + i * 256;
            int r = ch >> 3, c = ch & 7;
            uint32_t off = r * 128 + ((c ^ (r & 7)) << 4);
            cp16s(sK[buf] + off, kb + (size_t)(kv0 + r) * (3 * E_) + c * 8);
            cp16s(sV[buf] + off, vb + (size_t)(kv0 + r) * (3 * E_) + c * 8);
        }
    };
    loadKV(0, 0);
    cp_commit();
    asm volatile("cp.async.wait_group 0;\n");
    __syncthreads();

    uint32_t qf[4][4];
    {
        int r = warp * 16 + (lane & 7) + ((lane & 8) ? 8 : 0);
        int kc = ((lane & 16) ? 8 : 0);
        #pragma unroll
        for (int ks = 0; ks < 4; ks++)
            ldmx4(sQ + swz(r, ks * 16 + kc), qf[ks][0], qf[ks][1], qf[ks][2], qf[ks][3]);
    }

    float m0 = -1e30f, m1 = -1e30f;
    float l0 = 0.f, l1 = 0.f;
    float oacc[8][4];
    #pragma unroll
    for (int j = 0; j < 8; j++)
        #pragma unroll
        for (int c = 0; c < 4; c++) oacc[j][c] = 0.f;

    const int ITERS = N_ / 64;
    for (int it = 0; it < ITERS; ++it) {
        int cur = it & 1;
        if (it + 1 < ITERS) {
            loadKV(cur ^ 1, (it + 1) * 64);
            cp_commit();
            asm volatile("cp.async.wait_group 1;\n");
        } else {
            asm volatile("cp.async.wait_group 0;\n");
        }
        __syncthreads();

        float sacc[8][4];
        #pragma unroll
        for (int j = 0; j < 8; j++)
            #pragma unroll
            for (int c = 0; c < 4; c++) sacc[j][c] = 0.f;

        const int g = lane >> 3;
        #pragma unroll
        for (int j2 = 0; j2 < 4; j2++) {
            int nr = j2 * 16 + ((g >> 1) << 3) + (lane & 7);
            #pragma unroll
            for (int ks = 0; ks < 4; ks++) {
                uint32_t b0, b1, b2, b3;
                ldmx4(sK[cur] + swz(nr, ks * 16 + ((g & 1) << 3)), b0, b1, b2, b3);
                mma16816(sacc[2 * j2],     qf[ks], b0, b1);
                mma16816(sacc[2 * j2 + 1], qf[ks], b2, b3);
            }
        }

        float f0x[8], f0y[8], f1x[8], f1y[8];
        float mx0 = -1e30f, mx1 = -1e30f;
        #pragma unroll
        for (int j = 0; j < 8; j++) {
            __half2 h0 = __floats2half2_rn(sacc[j][0], sacc[j][1]);
            __half2 h1 = __floats2half2_rn(sacc[j][2], sacc[j][3]);
            float2 g0 = __half22float2(h0);
            float2 g1 = __half22float2(h1);
            f0x[j] = g0.x; f0y[j] = g0.y; f1x[j] = g1.x; f1y[j] = g1.y;
            mx0 = fmaxf(mx0, fmaxf(g0.x, g0.y));
            mx1 = fmaxf(mx1, fmaxf(g1.x, g1.y));
        }
        mx0 = fmaxf(mx0, __shfl_xor_sync(0xffffffffu, mx0, 1));
        mx0 = fmaxf(mx0, __shfl_xor_sync(0xffffffffu, mx0, 2));
        mx1 = fmaxf(mx1, __shfl_xor_sync(0xffffffffu, mx1, 1));
        mx1 = fmaxf(mx1, __shfl_xor_sync(0xffffffffu, mx1, 2));

        float m0n = fmaxf(m0, mx0), m1n = fmaxf(m1, mx1);
        float sc0 = __expf(m0 - m0n), sc1 = __expf(m1 - m1n);

        uint32_t pu0[8], pu1[8];
        float sum0 = 0.f, sum1 = 0.f;
        #pragma unroll
        for (int j = 0; j < 8; j++) {
            float p00 = __expf(f0x[j] - m0n), p01 = __expf(f0y[j] - m0n);
            float p10 = __expf(f1x[j] - m1n), p11 = __expf(f1y[j] - m1n);
            sum0 += p00 + p01;
            sum1 += p10 + p11;
            __half2 hp0 = __floats2half2_rn(p00, p01);
            __half2 hp1 = __floats2half2_rn(p10, p11);
            pu0[j] = *reinterpret_cast<uint32_t*>(&hp0);
            pu1[j] = *reinterpret_cast<uint32_t*>(&hp1);
        }
        sum0 += __shfl_xor_sync(0xffffffffu, sum0, 1);
        sum0 += __shfl_xor_sync(0xffffffffu, sum0, 2);
        sum1 += __shfl_xor_sync(0xffffffffu, sum1, 1);
        sum1 += __shfl_xor_sync(0xffffffffu, sum1, 2);

        l0 = l0 * sc0 + sum0;
        l1 = l1 * sc1 + sum1;
        m0 = m0n; m1 = m1n;

        #pragma unroll
        for (int j = 0; j < 8; j++) {
            oacc[j][0] *= sc0; oacc[j][1] *= sc0;
            oacc[j][2] *= sc1; oacc[j][3] *= sc1;
        }

        #pragma unroll
        for (int j2 = 0; j2 < 4; j2++) {
            int dc = j2 * 16 + ((g >> 1) << 3);
            #pragma unroll
            for (int kk = 0; kk < 4; kk++) {
                uint32_t b0, b1, b2, b3;
                ldmx4t(sV[cur] + swz(kk * 16 + ((g & 1) << 3) + (lane & 7), dc), b0, b1, b2, b3);
                uint32_t a[4] = { pu0[2 * kk], pu1[2 * kk], pu0[2 * kk + 1], pu1[2 * kk + 1] };
                mma16816(oacc[2 * j2],     a, b0, b1);
                mma16816(oacc[2 * j2 + 1], a, b2, b3);
            }
        }
        __syncthreads();
    }

    float inv0 = 1.0f / l0, inv1 = 1.0f / l1;
    int r0g = q0 + warp * 16 + (lane >> 2);
    int r1g = r0g + 8;
    __half* ob = outp + (size_t)b * N_ * E_ + h * 64 + (lane & 3) * 2;
    #pragma unroll
    for (int j = 0; j < 8; j++) {
        __half2 v0 = __floats2half2_rn(oacc[j][0] * inv0, oacc[j][1] * inv0);
        __half2 v1 = __floats2half2_rn(oacc[j][2] * inv1, oacc[j][3] * inv1);
        *reinterpret_cast<__half2*>(ob + (size_t)r0g * E_ + j * 8) = v0;
        *reinterpret_cast<__half2*>(ob + (size_t)r1g * E_ + j * 8) = v1;
    }
}

// ---------------- fp16 GEMM v2: raw mma, swizzled smem, 3-stage pipeline -----
// BM=128, BN=128, BK=64, 256 thr, warp tile 64x32 (2x4 warps). 2 CTAs/SM.
enum { EPI_F16 = 0, EPI_GELU = 1, EPI_RES = 2 };

template<int EPI>
__global__ __launch_bounds__(256, 2) void gemm2(
    const __half* __restrict__ A, int lda,
    const __half* __restrict__ Bm, int ldb,
    const __half* __restrict__ bias,
    void* __restrict__ Cout, int ldc,
    const float* __restrict__ res, int K)
{
    extern __shared__ __align__(128) char dynsmem[];
    __half* As = (__half*)dynsmem;                    // 3 stages * 128x64
    __half* Bs = (__half*)(dynsmem + 3 * 16384);      // 3 stages * 64x128

    const int tid = threadIdx.x;
    const int warp = tid >> 5, lane = tid & 31;
    const int wm = warp & 1, wn = warp >> 1;          // 2 x 4 warp grid
    const int rowBase = blockIdx.y * 128;
    const int colBase = blockIdx.x * 128;

    const uint32_t sA = (uint32_t)__cvta_generic_to_shared(As);
    const uint32_t sB = (uint32_t)__cvta_generic_to_shared(Bs);

    auto loadA = [&](int stg, int k0) {
        #pragma unroll
        for (int i = 0; i < 4; i++) {
            int ch = tid + i * 256;                    // 1024 x 16B
            int r = ch >> 3, c = ch & 7;
            cp16s(sA + stg * 16384 + r * 128 + ((c ^ (r & 7)) << 4),
                  A + (size_t)(rowBase + r) * lda + k0 + c * 8);
        }
    };
    auto loadB = [&](int stg, int k0) {
        #pragma unroll
        for (int i = 0; i < 4; i++) {
            int ch = tid + i * 256;                    // 64 rows x 16 chunks
            int r = ch >> 4, c = ch & 15;
            cp16s(sB + stg * 16384 + (c >> 3) * 8192 + r * 128 + (((c & 7) ^ (r & 7)) << 4),
                  Bm + (size_t)(k0 + r) * ldb + colBase + c * 8);
        }
    };

    float acc[4][4][4];
    #pragma unroll
    for (int mi = 0; mi < 4; mi++)
        #pragma unroll
        for (int j = 0; j < 4; j++)
            #pragma unroll
            for (int c = 0; c < 4; c++) acc[mi][j][c] = 0.f;

    const int KT = K / 64;
    loadA(0, 0);  loadB(0, 0);  cp_commit();
    loadA(1, 64); loadB(1, 64); cp_commit();

    const int g = lane >> 3;
    for (int it = 0; it < KT; ++it) {
        asm volatile("cp.async.wait_group 1;\n");
        __syncthreads();
        // safe: stage (it+2)%3 was consumed at iter it-1, done before this barrier
        if (it + 2 < KT) { loadA((it + 2) % 3, (it + 2) * 64); loadB((it + 2) % 3, (it + 2) * 64); cp_commit(); }

        const uint32_t aoff = sA + (it % 3) * 16384;
        const uint32_t boff = sB + (it % 3) * 16384;
        #pragma unroll
        for (int ks = 0; ks < 4; ks++) {
            uint32_t bf[2][4];
            #pragma unroll
            for (int j = 0; j < 2; j++) {
                int nn = wn * 32 + j * 16 + ((g >> 1) << 3);
                uint32_t addr = boff + (nn >> 6) * 8192
                              + swz(ks * 16 + ((g & 1) << 3) + (lane & 7), nn & 63);
                ldmx4t(addr, bf[j][0], bf[j][1], bf[j][2], bf[j][3]);
            }
            #pragma unroll
            for (int mi = 0; mi < 4; mi++) {
                uint32_t af[4];
                int r = wm * 64 + mi * 16 + (lane & 15);
                ldmx4(aoff + swz(r, ks * 16 + ((lane >> 4) << 3)), af[0], af[1], af[2], af[3]);
                mma16816(acc[mi][0], af, bf[0][0], bf[0][1]);
                mma16816(acc[mi][1], af, bf[0][2], bf[0][3]);
                mma16816(acc[mi][2], af, bf[1][0], bf[1][1]);
                mma16816(acc[mi][3], af, bf[1][2], bf[1][3]);
            }
        }
    }

    // ---- direct register epilogue ----
    #pragma unroll
    for (int mi = 0; mi < 4; mi++) {
        int gr0 = rowBase + wm * 64 + mi * 16 + (lane >> 2);
        int gr1 = gr0 + 8;
        #pragma unroll
        for (int j = 0; j < 4; j++) {
            int gc = colBase + wn * 32 + j * 8 + (lane & 3) * 2;
            float b0 = 0.f, b1 = 0.f;
            if (bias) {
                __half2 hb = *reinterpret_cast<const __half2*>(bias + gc);
                float2 fb = __half22float2(hb);
                b0 = fb.x; b1 = fb.y;
            }
            float v0 = acc[mi][j][0] + b0, v1 = acc[mi][j][1] + b1;
            float v2 = acc[mi][j][2] + b0, v3 = acc[mi][j][3] + b1;
            size_t o0 = (size_t)gr0 * ldc + gc;
            size_t o1 = (size_t)gr1 * ldc + gc;
            if (EPI == EPI_F16) {
                *reinterpret_cast<__half2*>((__half*)Cout + o0) = __floats2half2_rn(v0, v1);
                *reinterpret_cast<__half2*>((__half*)Cout + o1) = __floats2half2_rn(v2, v3);
            } else if (EPI == EPI_GELU) {
                float f0 = __half2float(__float2half(v0));
                float f1 = __half2float(__float2half(v1));
                float f2 = __half2float(__float2half(v2));
                float f3 = __half2float(__float2half(v3));
                float g0 = 0.5f * f0 * (1.0f + erff(f0 * 0.70710678118654752f));
                float g1 = 0.5f * f1 * (1.0f + erff(f1 * 0.70710678118654752f));
                float g2 = 0.5f * f2 * (1.0f + erff(f2 * 0.70710678118654752f));
                float g3 = 0.5f * f3 * (1.0f + erff(f3 * 0.70710678118654752f));
                *reinterpret_cast<__half2*>((__half*)Cout + o0) = __floats2half2_rn(g0, g1);
                *reinterpret_cast<__half2*>((__half*)Cout + o1) = __floats2half2_rn(g2, g3);
            } else { // EPI_RES: fp32 out = fp16(acc+bias) + residual
                float2 r0v = *reinterpret_cast<const float2*>(res + o0);
                float2 r1v = *reinterpret_cast<const float2*>(res + o1);
                float2 w0v, w1v;
                w0v.x = __half2float(__float2half(v0)) + r0v.x;
                w0v.y = __half2float(__float2half(v1)) + r0v.y;
                w1v.x = __half2float(__float2half(v2)) + r1v.x;
                w1v.y = __half2float(__float2half(v3)) + r1v.y;
                *reinterpret_cast<float2*>((float*)Cout + o0) = w0v;
                *reinterpret_cast<float2*>((float*)Cout + o1) = w1v;
            }
        }
    }
}

// ---------------- launch ----------------------------------------------------
#define GEMM_SMEM (3 * 16384 * 2)

extern "C" void kernel_launch(void* const* d_in, const int* in_sizes, int n_in,
                              void* d_out, int out_size)
{
    const float* x      = (const float*)d_in[0];
    const float* ln1_g  = (const float*)d_in[1];
    const float* ln1_b  = (const float*)d_in[2];
    const float* wqkv   = (const float*)d_in[3];
    const float* bqkv   = (const float*)d_in[4];
    const float* wproj  = (const float*)d_in[5];
    const float* bproj  = (const float*)d_in[6];
    const float* ln2_g  = (const float*)d_in[7];
    const float* ln2_b  = (const float*)d_in[8];
    const float* w0     = (const float*)d_in[9];
    const float* b0     = (const float*)d_in[10];
    const float* w1     = (const float*)d_in[11];
    const float* b1     = (const float*)d_in[12];

    void *p_h, *p_qkv, *p_attn, *p_res1, *p_h2, *p_z;
    void *p_wqkv, *p_wproj, *p_w0, *p_w1, *p_bqkv, *p_bproj, *p_b0, *p_b1;
    cudaGetSymbolAddress(&p_h, g_h);
    cudaGetSymbolAddress(&p_qkv, g_qkv);
    cudaGetSymbolAddress(&p_attn, g_attn);
    cudaGetSymbolAddress(&p_res1, g_res1);
    cudaGetSymbolAddress(&p_h2, g_h2);
    cudaGetSymbolAddress(&p_z, g_z);
    cudaGetSymbolAddress(&p_wqkv, g_wqkv);
    cudaGetSymbolAddress(&p_wproj, g_wproj);
    cudaGetSymbolAddress(&p_w0, g_w0);
    cudaGetSymbolAddress(&p_w1, g_w1);
    cudaGetSymbolAddress(&p_bqkv, g_bqkv);
    cudaGetSymbolAddress(&p_bproj, g_bproj);
    cudaGetSymbolAddress(&p_b0, g_b0);
    cudaGetSymbolAddress(&p_b1, g_b1);

    static bool attr_done = false;
    if (!attr_done) {
        cudaFuncSetAttribute(gemm2<EPI_F16>,  cudaFuncAttributeMaxDynamicSharedMemorySize, GEMM_SMEM);
        cudaFuncSetAttribute(gemm2<EPI_GELU>, cudaFuncAttributeMaxDynamicSharedMemorySize, GEMM_SMEM);
        cudaFuncSetAttribute(gemm2<EPI_RES>,  cudaFuncAttributeMaxDynamicSharedMemorySize, GEMM_SMEM);
        attr_done = true;
    }

    auto cast = [&](const float* src, void* dst, int n) {
        int blocks = (n + 255) / 256;
        if (blocks > 4096) blocks = 4096;
        cast_f2h<<<blocks, 256>>>(src, (__half*)dst, n);
    };
    cast(wqkv,  p_wqkv,  E_ * 3 * E_);
    cast(bqkv,  p_bqkv,  3 * E_);
    cast(wproj, p_wproj, E_ * E_);
    cast(bproj, p_bproj, E_);
    cast(w0,    p_w0,    E_ * HID_);
    cast(b0,    p_b0,    HID_);
    cast(w1,    p_w1,    HID_ * E_);
    cast(b1,    p_b1,    E_);

    // LN1
    ln_kernel<<<M_, 256>>>(x, ln1_g, ln1_b, (__half*)p_h);

    // QKV: [8192,1024] @ [1024,3072]
    gemm2<EPI_F16><<<dim3(3 * E_ / 128, M_ / 128), 256, GEMM_SMEM>>>(
        (const __half*)p_h, E_, (const __half*)p_wqkv, 3 * E_,
        (const __half*)p_bqkv, p_qkv, 3 * E_, nullptr, E_);

    // fused flash attention
    flash_attn_kernel<<<dim3(N_ / 128, B_ * H_), 256>>>(
        (const __half*)p_qkv, (__half*)p_attn);

    // proj + residual (fp32 out): res1 = fp16(attn@wproj + bproj) + x
    gemm2<EPI_RES><<<dim3(E_ / 128, M_ / 128), 256, GEMM_SMEM>>>(
        (const __half*)p_attn, E_, (const __half*)p_wproj, E_,
        (const __half*)p_bproj, p_res1, E_, x, E_);

    // LN2
    ln_kernel<<<M_, 256>>>((const float*)p_res1, ln2_g, ln2_b, (__half*)p_h2);

    // MLP up + gelu
    gemm2<EPI_GELU><<<dim3(HID_ / 128, M_ / 128), 256, GEMM_SMEM>>>(
        (const __half*)p_h2, E_, (const __half*)p_w0, HID_,
        (const __half*)p_b0, p_z, HID_, nullptr, E_);

    // MLP down + residual (fp32 out)
    gemm2<EPI_RES><<<dim3(E_ / 128, M_ / 128), 256, GEMM_SMEM>>>(
        (const __half*)p_z, HID_, (const __half*)p_w1, E_,
        (const __half*)p_b1, d_out, E_, (const float*)p_res1, HID_);
}